// round 14
// baseline (speedup 1.0000x reference)
#include <cuda_runtime.h>
#include <cuda_bf16.h>
#include <math.h>

#define B_TOK 32768
#define D_DIM 128
#define H_DIM 512
#define E_EXP 16
#define TM 64
#define NH 32
#define NCHUNK (H_DIM / NH)   // 16
#define THREADS 256
#define MAX_TILES 544         // >= 512 + 15 worst case

// weight image sizes (bytes)
#define W1HALF 8704           // 32 h-rows x 272B (64 d-pair words + 4 pad words)
#define W1CH   (2 * W1HALF)   // 17408 (hi + lo)
#define W2HALF 10240          // 128 d-rows x 80B (16 j-pair words + 4 pad words)
#define W2CH   (2 * W2HALF)   // 20480
#define CHUNK_BYTES (W1CH + W2CH)  // 37888

// SMEM layout (bytes)
#define OFF_TOKS 0
#define OFF_XH   256
#define OFF_XL   (OFF_XH + 17408)
#define OFF_A2H  (OFF_XL + 17408)
#define OFF_A2L  (OFF_A2H + 5120)
#define OFF_W1   (OFF_A2L + 5120)            // double buffer: + buf*W1CH, each [H|L]
#define OFF_W2   (OFF_W1 + 2 * W1CH)         // single buffer: [H|L]
#define SMEM_TOTAL (OFF_W2 + W2CH)           // 100608 -> 2 CTAs/SM

// ---------------- device scratch ----------------
__device__ int g_cnt[E_EXP];
__device__ int g_tok[E_EXP * B_TOK];
__device__ int g_ntiles;
__device__ int g_tile[MAX_TILES];
__device__ unsigned char g_wt[E_EXP][NCHUNK][CHUNK_BYTES];  // pre-split weight images

// ---------------- helpers ----------------
__device__ __forceinline__ void bsplit2(float v0, float v1, unsigned& hi, unsigned& lo) {
    __nv_bfloat162 h = __floats2bfloat162_rn(v0, v1);
    float r0 = v0 - __bfloat162float(h.x);
    float r1 = v1 - __bfloat162float(h.y);
    __nv_bfloat162 l = __floats2bfloat162_rn(r0, r1);
    hi = *(unsigned*)&h;
    lo = *(unsigned*)&l;
}
__device__ __forceinline__ float gelu(float h) {
    return 0.5f * h * (1.0f + erff(h * 0.70710678118654752440f));
}
__device__ __forceinline__ unsigned smem_u32(const void* p) {
    unsigned a;
    asm("{ .reg .u64 t; cvta.to.shared.u64 t, %1; cvt.u32.u64 %0, t; }"
        : "=r"(a) : "l"(p));
    return a;
}
__device__ __forceinline__ void cp_async16(unsigned dst, const void* src) {
    asm volatile("cp.async.cg.shared.global [%0], [%1], 16;"
                 :: "r"(dst), "l"(src) : "memory");
}
#define CP_COMMIT() asm volatile("cp.async.commit_group;" ::: "memory")
#define CP_WAIT(n)  asm volatile("cp.async.wait_group %0;" :: "n"(n) : "memory")

// ldmatrix x4: four 8x8 b16 tiles, one per 8-thread address group
__device__ __forceinline__ void ldsm4(unsigned addr, unsigned* r) {
    asm volatile("ldmatrix.sync.aligned.m8n8.x4.shared.b16 {%0,%1,%2,%3}, [%4];"
                 : "=r"(r[0]), "=r"(r[1]), "=r"(r[2]), "=r"(r[3]) : "r"(addr));
}

// D += A * B  (m16n8k16, bf16 in, fp32 acc) — base-PTX HMMA, valid on sm_103
__device__ __forceinline__ void mma16816(float* c, const unsigned* a, const unsigned* b) {
    asm volatile(
        "mma.sync.aligned.m16n8k16.row.col.f32.bf16.bf16.f32 "
        "{%0,%1,%2,%3}, {%4,%5,%6,%7}, {%8,%9}, {%0,%1,%2,%3};"
        : "+f"(c[0]), "+f"(c[1]), "+f"(c[2]), "+f"(c[3])
        : "r"(a[0]), "r"(a[1]), "r"(a[2]), "r"(a[3]), "r"(b[0]), "r"(b[1]));
}

// ---------------- kernel P: pre-split weights + zero counters ----------------
__global__ __launch_bounds__(THREADS) void prep_kernel(
    const float* __restrict__ w1, const float* __restrict__ w2) {
    if (blockIdx.x == 0 && blockIdx.y == 0 && threadIdx.x < E_EXP)
        g_cnt[threadIdx.x] = 0;
    int e = blockIdx.x, c = blockIdx.y;
    int h0 = c * NH;
    const float* w1e = w1 + (size_t)e * D_DIM * H_DIM;
    const float* w2e = w2 + (size_t)e * H_DIM * D_DIM;
    unsigned char* dst = g_wt[e][c];

    for (int i = threadIdx.x; i < W1HALF / 4; i += THREADS) {  // 2176 words
        int h = i / 68, w = i % 68;
        if (w < 64) {
            float v0 = w1e[(size_t)(2 * w) * H_DIM + h0 + h];
            float v1 = w1e[(size_t)(2 * w + 1) * H_DIM + h0 + h];
            unsigned hi, lo;
            bsplit2(v0, v1, hi, lo);
            *(unsigned*)(dst + i * 4) = hi;
            *(unsigned*)(dst + W1HALF + i * 4) = lo;
        }
    }
    for (int i = threadIdx.x; i < W2HALF / 4; i += THREADS) {  // 2560 words
        int d = i / 20, w = i % 20;
        if (w < 16) {
            float v0 = w2e[(size_t)(h0 + 2 * w) * D_DIM + d];
            float v1 = w2e[(size_t)(h0 + 2 * w + 1) * D_DIM + d];
            unsigned hi, lo;
            bsplit2(v0, v1, hi, lo);
            *(unsigned*)(dst + W1CH + i * 4) = hi;
            *(unsigned*)(dst + W1CH + W2HALF + i * 4) = lo;
        }
    }
}

// ---------------- kernel 1: router (known-good) ----------------
__global__ __launch_bounds__(THREADS) void router_kernel(
    const float* __restrict__ x, const float* __restrict__ wg,
    const float* __restrict__ bg) {
    __shared__ float wgs[D_DIM * E_EXP];
    __shared__ float bgs[E_EXP];
    int tid = threadIdx.x;
    for (int i = tid; i < D_DIM * E_EXP; i += THREADS) wgs[i] = wg[i];
    if (tid < E_EXP) bgs[tid] = bg[tid];
    __syncthreads();

    int b = blockIdx.x * THREADS + tid;
    float acc[E_EXP];
#pragma unroll
    for (int e = 0; e < E_EXP; e++) acc[e] = bgs[e];
    const float4* xr = reinterpret_cast<const float4*>(x) + (size_t)b * (D_DIM / 4);
#pragma unroll 4
    for (int dq = 0; dq < D_DIM / 4; dq++) {
        float4 xv = xr[dq];
#pragma unroll
        for (int e = 0; e < E_EXP; e++) {
            acc[e] += xv.x * wgs[(dq * 4 + 0) * E_EXP + e];
            acc[e] += xv.y * wgs[(dq * 4 + 1) * E_EXP + e];
            acc[e] += xv.z * wgs[(dq * 4 + 2) * E_EXP + e];
            acc[e] += xv.w * wgs[(dq * 4 + 3) * E_EXP + e];
        }
    }
    int best = 0; float bv = acc[0];
#pragma unroll
    for (int e = 1; e < E_EXP; e++)
        if (acc[e] > bv) { bv = acc[e]; best = e; }

    unsigned lane = tid & 31;
    unsigned mask = __match_any_sync(0xffffffffu, best);
    int leader = __ffs(mask) - 1;
    int rank = __popc(mask & ((1u << lane) - 1u));
    int base = 0;
    if ((int)lane == leader) base = atomicAdd(&g_cnt[best], __popc(mask));
    base = __shfl_sync(0xffffffffu, base, leader);
    g_tok[best * B_TOK + base + rank] = b;
}

// ---------------- kernel T: build exact tile list ----------------
__global__ __launch_bounds__(THREADS) void tile_kernel() {
    __shared__ int offs[E_EXP + 1];
    int tid = threadIdx.x;
    if (tid == 0) {
        int s = 0;
#pragma unroll
        for (int e = 0; e < E_EXP; e++) {
            offs[e] = s;
            s += (g_cnt[e] + TM - 1) / TM;
        }
        offs[E_EXP] = s;
        g_ntiles = s;
    }
    __syncthreads();
#pragma unroll
    for (int e = 0; e < E_EXP; e++) {
        int o = offs[e], nt = offs[e + 1] - o;
        for (int i = tid; i < nt; i += THREADS)
            g_tile[o + i] = (e << 16) | i;
    }
}

// ---------------- kernel 2: grouped MLP on HMMA + LDSM, 2 CTAs/SM ----------------
__global__ __launch_bounds__(THREADS, 2) void moe_mma_kernel(
    const float* __restrict__ x, float* __restrict__ out) {
    extern __shared__ char smem[];
    int b = blockIdx.x;
    if (b >= g_ntiles) return;
    int desc = g_tile[b];
    int e = desc >> 16;
    int start = (desc & 0xffff) * TM;
    int cnt = g_cnt[e];
    int ntok = min(TM, cnt - start);
    int tid = threadIdx.x, wid = tid >> 5, lane = tid & 31;
    int g = lane >> 2, tg = lane & 3;
    int m0 = (wid & 3) * 16;
    int n0a = (wid >> 2) * 16;  // GEMM1 n-offset (32 cols over 2 warp groups)
    int n0b = (wid >> 2) * 64;  // GEMM2 n-offset (128 cols over 2 warp groups)
    unsigned sb = smem_u32(smem);

    int* toks = (int*)(smem + OFF_TOKS);
    if (tid < TM) toks[tid] = (tid < ntok) ? g_tok[e * B_TOK + start + tid] : -1;
    __syncthreads();

    // ---- gather X tile [64][128] fp32 -> split bf16 hi/lo (row stride 272B)
    {
        int m = tid >> 2, q4 = tid & 3;
        int t = toks[m];
        const float4* xr = reinterpret_cast<const float4*>(x) +
                           (size_t)(t < 0 ? 0 : t) * 32 + q4 * 8;
#pragma unroll
        for (int i = 0; i < 8; i++) {
            float4 v = (t >= 0) ? xr[i] : make_float4(0.f, 0.f, 0.f, 0.f);
            int d = q4 * 32 + i * 4;
            unsigned hi, lo;
            bsplit2(v.x, v.y, hi, lo);
            *(unsigned*)(smem + OFF_XH + m * 272 + d * 2) = hi;
            *(unsigned*)(smem + OFF_XL + m * 272 + d * 2) = lo;
            bsplit2(v.z, v.w, hi, lo);
            *(unsigned*)(smem + OFF_XH + m * 272 + d * 2 + 4) = hi;
            *(unsigned*)(smem + OFF_XL + m * 272 + d * 2 + 4) = lo;
        }
    }

    // ---- prologue: prefetch W1(0) into w1 buffer 0
    {
        const unsigned char* src = g_wt[e][0];
        unsigned dst = sb + OFF_W1;
        for (int i = tid; i < W1CH / 16; i += THREADS)
            cp_async16(dst + i * 16, src + i * 16);
        CP_COMMIT();
    }

    // ---- per-thread LDSM base addresses (hoisted out of all loops)
    unsigned xa = sb + OFF_XH +
                  (unsigned)(m0 + ((lane >> 3) & 1) * 8 + (lane & 7)) * 272 +
                  ((lane >> 4) & 1) * 16;
    unsigned xla = xa + (OFF_XL - OFF_XH);
    unsigned b1off = (unsigned)(n0a + ((lane >> 4) & 1) * 8 + (lane & 7)) * 272 +
                     ((lane >> 3) & 1) * 16;
    unsigned a2a = sb + OFF_A2H +
                   (unsigned)(m0 + ((lane >> 3) & 1) * 8 + (lane & 7)) * 80 +
                   ((lane >> 4) & 1) * 16;
    unsigned a2la = a2a + (OFF_A2L - OFF_A2H);
    unsigned b2a = sb + OFF_W2 +
                   (unsigned)(n0b + ((lane >> 4) & 1) * 8 + (lane & 7)) * 80 +
                   ((lane >> 3) & 1) * 16;

    float oacc[8][4];
#pragma unroll
    for (int i = 0; i < 8; i++)
#pragma unroll
        for (int j = 0; j < 4; j++) oacc[i][j] = 0.f;

    for (int c = 0; c < NCHUNK; c++) {
        __syncthreads();  // prev GEMM2 readers of W2/A2 done; X stores done (c==0)

        // issue W2(c) copy (overlaps GEMM1), then W1(c+1) prefetch
        {
            const unsigned char* s2 = g_wt[e][c] + W1CH;
            unsigned d2 = sb + OFF_W2;
            for (int i = tid; i < W2CH / 16; i += THREADS)
                cp_async16(d2 + i * 16, s2 + i * 16);
            CP_COMMIT();
            int cn = (c + 1) & (NCHUNK - 1);   // last iter: harmless dummy refetch
            const unsigned char* s1 = g_wt[e][cn];
            unsigned d1 = sb + OFF_W1 + ((c + 1) & 1) * W1CH;
            for (int i = tid; i < W1CH / 16; i += THREADS)
                cp_async16(d1 + i * 16, s1 + i * 16);
            CP_COMMIT();
        }
        CP_WAIT(2);       // W1(c) complete (this thread)
        __syncthreads();  // W1(c) visible to all

        unsigned w1b = sb + OFF_W1 + (c & 1) * W1CH + b1off;

        // ---- GEMM1: C1[16x16 per warp] = X @ W1c^T, 3-MMA split, K=128
        float acc1[2][4];
#pragma unroll
        for (int i = 0; i < 2; i++)
#pragma unroll
            for (int j = 0; j < 4; j++) acc1[i][j] = 0.f;

#pragma unroll
        for (int s = 0; s < 8; s++) {
            unsigned ah[4], al[4], bh[4], bl[4];
            ldsm4(xa + s * 32, ah);
            ldsm4(xla + s * 32, al);
            ldsm4(w1b + s * 32, bh);
            ldsm4(w1b + W1HALF + s * 32, bl);
            mma16816(acc1[0], ah, bh);
            mma16816(acc1[0], ah, bl);
            mma16816(acc1[0], al, bh);
            mma16816(acc1[1], ah, bh + 2);
            mma16816(acc1[1], ah, bl + 2);
            mma16816(acc1[1], al, bh + 2);
        }

        // ---- GELU + split -> A2[m][h] hi/lo (row stride 80B)
#pragma unroll
        for (int nf = 0; nf < 2; nf++) {
            int col = n0a + nf * 8 + tg * 2;
            unsigned hi, lo;
            bsplit2(gelu(acc1[nf][0]), gelu(acc1[nf][1]), hi, lo);
            *(unsigned*)(smem + OFF_A2H + (m0 + g) * 80 + col * 2) = hi;
            *(unsigned*)(smem + OFF_A2L + (m0 + g) * 80 + col * 2) = lo;
            bsplit2(gelu(acc1[nf][2]), gelu(acc1[nf][3]), hi, lo);
            *(unsigned*)(smem + OFF_A2H + (m0 + g + 8) * 80 + col * 2) = hi;
            *(unsigned*)(smem + OFF_A2L + (m0 + g + 8) * 80 + col * 2) = lo;
        }
        CP_WAIT(1);       // W2(c) complete (W1(c+1) still pending)
        __syncthreads();  // A2 + W2 visible

        // ---- GEMM2: out[16x64 per warp] += gelu(H) @ W2c^T, K=32
#pragma unroll
        for (int s = 0; s < 2; s++) {
            unsigned ah[4], al[4];
            ldsm4(a2a + s * 32, ah);
            ldsm4(a2la + s * 32, al);
#pragma unroll
            for (int q = 0; q < 4; q++) {
                unsigned bh[4], bl[4];
                ldsm4(b2a + q * 1280 + s * 32, bh);
                ldsm4(b2a + W2HALF + q * 1280 + s * 32, bl);
                mma16816(oacc[2 * q], ah, bh);
                mma16816(oacc[2 * q], ah, bl);
                mma16816(oacc[2 * q], al, bh);
                mma16816(oacc[2 * q + 1], ah, bh + 2);
                mma16816(oacc[2 * q + 1], ah, bl + 2);
                mma16816(oacc[2 * q + 1], al, bh + 2);
            }
        }
    }

    // ---- scatter output rows
#pragma unroll
    for (int nf = 0; nf < 8; nf++) {
        int col = n0b + nf * 8 + tg * 2;
        int m1 = m0 + g, m2 = m0 + g + 8;
        if (m1 < ntok) {
            int t = toks[m1];
            *reinterpret_cast<float2*>(out + (size_t)t * D_DIM + col) =
                make_float2(oacc[nf][0], oacc[nf][1]);
        }
        if (m2 < ntok) {
            int t = toks[m2];
            *reinterpret_cast<float2*>(out + (size_t)t * D_DIM + col) =
                make_float2(oacc[nf][2], oacc[nf][3]);
        }
    }
}

// ---------------- launcher ----------------
extern "C" void kernel_launch(void* const* d_in, const int* in_sizes, int n_in,
                              void* d_out, int out_size) {
    const float* x  = (const float*)d_in[0];
    const float* w1 = (const float*)d_in[1];
    const float* w2 = (const float*)d_in[2];
    const float* wg = (const float*)d_in[3];
    const float* bg = (const float*)d_in[4];
    float* out = (float*)d_out;

    cudaFuncSetAttribute(moe_mma_kernel, cudaFuncAttributeMaxDynamicSharedMemorySize,
                         SMEM_TOTAL);

    dim3 pgrid(E_EXP, NCHUNK);
    prep_kernel<<<pgrid, THREADS>>>(w1, w2);   // also zeroes g_cnt (block 0,0)
    router_kernel<<<B_TOK / THREADS, THREADS>>>(x, wg, bg);
    tile_kernel<<<1, THREADS>>>();
    moe_mma_kernel<<<MAX_TILES, THREADS, SMEM_TOTAL>>>(x, out);
}

// round 15
// speedup vs baseline: 1.0050x; 1.0050x over previous
#include <cuda_runtime.h>
#include <cuda_bf16.h>
#include <math.h>

#define B_TOK 32768
#define D_DIM 128
#define H_DIM 512
#define E_EXP 16
#define TM 64
#define NH 32
#define NCHUNK (H_DIM / NH)   // 16
#define THREADS 256
#define MAX_TILES 544

// weight image sizes (bytes)
#define W1HALF 8704           // 32 h-rows x 272B (64 d-pair words + 4 pad words)
#define W1CH   (2 * W1HALF)   // 17408 (hi + lo)
#define W2HALF 10240          // 128 d-rows x 80B (16 j-pair words + 4 pad words)
#define W2CH   (2 * W2HALF)   // 20480
#define CHUNK_BYTES (W1CH + W2CH)  // 37888

// SMEM layout (bytes)
#define OFF_TOKS 0
#define OFF_XH   256
#define OFF_XL   (OFF_XH + 17408)            // 17664
#define OFF_A2   (OFF_XL + 17408)            // 35072: 2 bufs x (H 5120 | L 5120)
#define A2BUF    10240
#define OFF_W1   (OFF_A2 + 2 * A2BUF)        // 55552: 2 bufs x W1CH
#define OFF_W2   (OFF_W1 + 2 * W1CH)         // 90368: single W2CH
#define SMEM_TOTAL (OFF_W2 + W2CH)           // 110848 -> 2 CTAs/SM

// ---------------- device scratch ----------------
__device__ int g_cnt[E_EXP];
__device__ int g_tok[E_EXP * B_TOK];
__device__ int g_ntiles;
__device__ int g_tile[MAX_TILES];
__device__ unsigned char g_wt[E_EXP][NCHUNK][CHUNK_BYTES];  // pre-split weight images

// ---------------- helpers ----------------
__device__ __forceinline__ void bsplit2(float v0, float v1, unsigned& hi, unsigned& lo) {
    __nv_bfloat162 h = __floats2bfloat162_rn(v0, v1);
    float r0 = v0 - __bfloat162float(h.x);
    float r1 = v1 - __bfloat162float(h.y);
    __nv_bfloat162 l = __floats2bfloat162_rn(r0, r1);
    hi = *(unsigned*)&h;
    lo = *(unsigned*)&l;
}
__device__ __forceinline__ float gelu(float h) {
    return 0.5f * h * (1.0f + erff(h * 0.70710678118654752440f));
}
__device__ __forceinline__ unsigned smem_u32(const void* p) {
    unsigned a;
    asm("{ .reg .u64 t; cvta.to.shared.u64 t, %1; cvt.u32.u64 %0, t; }"
        : "=r"(a) : "l"(p));
    return a;
}
__device__ __forceinline__ void cp_async16(unsigned dst, const void* src) {
    asm volatile("cp.async.cg.shared.global [%0], [%1], 16;"
                 :: "r"(dst), "l"(src) : "memory");
}
#define CP_COMMIT() asm volatile("cp.async.commit_group;" ::: "memory")
#define CP_WAIT(n)  asm volatile("cp.async.wait_group %0;" :: "n"(n) : "memory")

// ldmatrix x4: four 8x8 b16 tiles, one per 8-thread address group
__device__ __forceinline__ void ldsm4(unsigned addr, unsigned* r) {
    asm volatile("ldmatrix.sync.aligned.m8n8.x4.shared.b16 {%0,%1,%2,%3}, [%4];"
                 : "=r"(r[0]), "=r"(r[1]), "=r"(r[2]), "=r"(r[3]) : "r"(addr));
}

// D += A * B  (m16n8k16, bf16 in, fp32 acc) — base-PTX HMMA, valid on sm_103
__device__ __forceinline__ void mma16816(float* c, const unsigned* a, const unsigned* b) {
    asm volatile(
        "mma.sync.aligned.m16n8k16.row.col.f32.bf16.bf16.f32 "
        "{%0,%1,%2,%3}, {%4,%5,%6,%7}, {%8,%9}, {%0,%1,%2,%3};"
        : "+f"(c[0]), "+f"(c[1]), "+f"(c[2]), "+f"(c[3])
        : "r"(a[0]), "r"(a[1]), "r"(a[2]), "r"(a[3]), "r"(b[0]), "r"(b[1]));
}

// ---------------- kernel P: pre-split weights + zero counters ----------------
__global__ __launch_bounds__(THREADS) void prep_kernel(
    const float* __restrict__ w1, const float* __restrict__ w2) {
    if (blockIdx.x == 0 && blockIdx.y == 0 && threadIdx.x < E_EXP)
        g_cnt[threadIdx.x] = 0;
    int e = blockIdx.x, c = blockIdx.y;
    int h0 = c * NH;
    const float* w1e = w1 + (size_t)e * D_DIM * H_DIM;
    const float* w2e = w2 + (size_t)e * H_DIM * D_DIM;
    unsigned char* dst = g_wt[e][c];

    for (int i = threadIdx.x; i < W1HALF / 4; i += THREADS) {  // 2176 words
        int h = i / 68, w = i % 68;
        if (w < 64) {
            float v0 = w1e[(size_t)(2 * w) * H_DIM + h0 + h];
            float v1 = w1e[(size_t)(2 * w + 1) * H_DIM + h0 + h];
            unsigned hi, lo;
            bsplit2(v0, v1, hi, lo);
            *(unsigned*)(dst + i * 4) = hi;
            *(unsigned*)(dst + W1HALF + i * 4) = lo;
        }
    }
    for (int i = threadIdx.x; i < W2HALF / 4; i += THREADS) {  // 2560 words
        int d = i / 20, w = i % 20;
        if (w < 16) {
            float v0 = w2e[(size_t)(h0 + 2 * w) * D_DIM + d];
            float v1 = w2e[(size_t)(h0 + 2 * w + 1) * D_DIM + d];
            unsigned hi, lo;
            bsplit2(v0, v1, hi, lo);
            *(unsigned*)(dst + W1CH + i * 4) = hi;
            *(unsigned*)(dst + W1CH + W2HALF + i * 4) = lo;
        }
    }
}

// ---------------- kernel 1: router (known-good) ----------------
__global__ __launch_bounds__(THREADS) void router_kernel(
    const float* __restrict__ x, const float* __restrict__ wg,
    const float* __restrict__ bg) {
    __shared__ float wgs[D_DIM * E_EXP];
    __shared__ float bgs[E_EXP];
    int tid = threadIdx.x;
    for (int i = tid; i < D_DIM * E_EXP; i += THREADS) wgs[i] = wg[i];
    if (tid < E_EXP) bgs[tid] = bg[tid];
    __syncthreads();

    int b = blockIdx.x * THREADS + tid;
    float acc[E_EXP];
#pragma unroll
    for (int e = 0; e < E_EXP; e++) acc[e] = bgs[e];
    const float4* xr = reinterpret_cast<const float4*>(x) + (size_t)b * (D_DIM / 4);
#pragma unroll 4
    for (int dq = 0; dq < D_DIM / 4; dq++) {
        float4 xv = xr[dq];
#pragma unroll
        for (int e = 0; e < E_EXP; e++) {
            acc[e] += xv.x * wgs[(dq * 4 + 0) * E_EXP + e];
            acc[e] += xv.y * wgs[(dq * 4 + 1) * E_EXP + e];
            acc[e] += xv.z * wgs[(dq * 4 + 2) * E_EXP + e];
            acc[e] += xv.w * wgs[(dq * 4 + 3) * E_EXP + e];
        }
    }
    int best = 0; float bv = acc[0];
#pragma unroll
    for (int e = 1; e < E_EXP; e++)
        if (acc[e] > bv) { bv = acc[e]; best = e; }

    unsigned lane = tid & 31;
    unsigned mask = __match_any_sync(0xffffffffu, best);
    int leader = __ffs(mask) - 1;
    int rank = __popc(mask & ((1u << lane) - 1u));
    int base = 0;
    if ((int)lane == leader) base = atomicAdd(&g_cnt[best], __popc(mask));
    base = __shfl_sync(0xffffffffu, base, leader);
    g_tok[best * B_TOK + base + rank] = b;
}

// ---------------- kernel T: build exact tile list ----------------
__global__ __launch_bounds__(THREADS) void tile_kernel() {
    __shared__ int offs[E_EXP + 1];
    int tid = threadIdx.x;
    if (tid == 0) {
        int s = 0;
#pragma unroll
        for (int e = 0; e < E_EXP; e++) {
            offs[e] = s;
            s += (g_cnt[e] + TM - 1) / TM;
        }
        offs[E_EXP] = s;
        g_ntiles = s;
    }
    __syncthreads();
#pragma unroll
    for (int e = 0; e < E_EXP; e++) {
        int o = offs[e], nt = offs[e + 1] - o;
        for (int i = tid; i < nt; i += THREADS)
            g_tile[o + i] = (e << 16) | i;
    }
}

// ---------------- kernel 2: pipelined grouped MLP (HMMA + LDSM, 2 CTAs/SM) --------
__global__ __launch_bounds__(THREADS, 2) void moe_mma_kernel(
    const float* __restrict__ x, float* __restrict__ out) {
    extern __shared__ char smem[];
    int b = blockIdx.x;
    if (b >= g_ntiles) return;
    int desc = g_tile[b];
    int e = desc >> 16;
    int start = (desc & 0xffff) * TM;
    int cnt = g_cnt[e];
    int ntok = min(TM, cnt - start);
    int tid = threadIdx.x, wid = tid >> 5, lane = tid & 31;
    int g = lane >> 2, tg = lane & 3;
    int m0 = (wid & 3) * 16;
    int n0a = (wid >> 2) * 16;  // GEMM1 n-offset
    int n0b = (wid >> 2) * 64;  // GEMM2 n-offset
    unsigned sb = smem_u32(smem);

    int* toks = (int*)(smem + OFF_TOKS);
    if (tid < TM) toks[tid] = (tid < ntok) ? g_tok[e * B_TOK + start + tid] : -1;
    __syncthreads();

    // ---- prologue: issue W1(0) copy (overlaps X gather)
    {
        const unsigned char* src = g_wt[e][0];
        unsigned dst = sb + OFF_W1;
        for (int i = tid; i < W1CH / 16; i += THREADS)
            cp_async16(dst + i * 16, src + i * 16);
        CP_COMMIT();
    }

    // ---- gather X tile [64][128] fp32 -> split bf16 hi/lo (row stride 272B)
    {
        int m = tid >> 2, q4 = tid & 3;
        int t = toks[m];
        const float4* xr = reinterpret_cast<const float4*>(x) +
                           (size_t)(t < 0 ? 0 : t) * 32 + q4 * 8;
#pragma unroll
        for (int i = 0; i < 8; i++) {
            float4 v = (t >= 0) ? xr[i] : make_float4(0.f, 0.f, 0.f, 0.f);
            int d = q4 * 32 + i * 4;
            unsigned hi, lo;
            bsplit2(v.x, v.y, hi, lo);
            *(unsigned*)(smem + OFF_XH + m * 272 + d * 2) = hi;
            *(unsigned*)(smem + OFF_XL + m * 272 + d * 2) = lo;
            bsplit2(v.z, v.w, hi, lo);
            *(unsigned*)(smem + OFF_XH + m * 272 + d * 2 + 4) = hi;
            *(unsigned*)(smem + OFF_XL + m * 272 + d * 2 + 4) = lo;
        }
    }
    CP_WAIT(0);   // W1(0) complete (this thread)

    // ---- per-thread LDSM base addresses (hoisted)
    unsigned xa = sb + OFF_XH +
                  (unsigned)(m0 + ((lane >> 3) & 1) * 8 + (lane & 7)) * 272 +
                  ((lane >> 4) & 1) * 16;
    unsigned xla = xa + (OFF_XL - OFF_XH);
    unsigned b1off = (unsigned)(n0a + ((lane >> 4) & 1) * 8 + (lane & 7)) * 272 +
                     ((lane >> 3) & 1) * 16;
    unsigned a2row = (unsigned)(m0 + ((lane >> 3) & 1) * 8 + (lane & 7)) * 80 +
                     ((lane >> 4) & 1) * 16;   // add OFF_A2 + parity*A2BUF (+5120 for L)
    unsigned b2a = sb + OFF_W2 +
                   (unsigned)(n0b + ((lane >> 4) & 1) * 8 + (lane & 7)) * 80 +
                   ((lane >> 3) & 1) * 16;

    float oacc[8][4];
#pragma unroll
    for (int i = 0; i < 8; i++)
#pragma unroll
        for (int j = 0; j < 4; j++) oacc[i][j] = 0.f;

    for (int c = 0; c < NCHUNK; c++) {
        __syncthreads();  // all prev copies/epilogue visible; W1 buf[(c+1)&1] + A2[c&1] free

        // G1: prefetch W1(c+1) into the other W1 buffer (overlaps GEMM2 + GEMM1)
        {
            int cn = (c + 1) & (NCHUNK - 1);
            const unsigned char* s1 = g_wt[e][cn];
            unsigned d1 = sb + OFF_W1 + ((c + 1) & 1) * W1CH;
            for (int i = tid; i < W1CH / 16; i += THREADS)
                cp_async16(d1 + i * 16, s1 + i * 16);
            CP_COMMIT();
        }

        // ---- GEMM2(c-1): oacc += gelu(H(c-1)) @ W2(c-1)^T   [A2 parity (c-1)&1]
        if (c > 0) {
            unsigned a2h = sb + OFF_A2 + (unsigned)((c - 1) & 1) * A2BUF + a2row;
            unsigned a2l = a2h + 5120;
#pragma unroll
            for (int s = 0; s < 2; s++) {
                unsigned ah[4], al[4];
                ldsm4(a2h + s * 32, ah);
                ldsm4(a2l + s * 32, al);
#pragma unroll
                for (int q = 0; q < 4; q++) {
                    unsigned bh[4], bl[4];
                    ldsm4(b2a + q * 1280 + s * 32, bh);
                    ldsm4(b2a + W2HALF + q * 1280 + s * 32, bl);
                    mma16816(oacc[2 * q], ah, bh);
                    mma16816(oacc[2 * q], ah, bl);
                    mma16816(oacc[2 * q], al, bh);
                    mma16816(oacc[2 * q + 1], ah, bh + 2);
                    mma16816(oacc[2 * q + 1], ah, bl + 2);
                    mma16816(oacc[2 * q + 1], al, bh + 2);
                }
            }
        }
        __syncthreads();  // W2 buffer free (all warps done with W2(c-1))

        // G2: copy W2(c) (overlaps GEMM1)
        {
            const unsigned char* s2 = g_wt[e][c] + W1CH;
            unsigned d2 = sb + OFF_W2;
            for (int i = tid; i < W2CH / 16; i += THREADS)
                cp_async16(d2 + i * 16, s2 + i * 16);
            CP_COMMIT();
        }

        unsigned w1b = sb + OFF_W1 + (c & 1) * W1CH + b1off;

        // ---- GEMM1(c): 3-way split accumulators (6 independent chains)
        float a1h[2][4], a1m[2][4], a1l[2][4];
#pragma unroll
        for (int i = 0; i < 2; i++)
#pragma unroll
            for (int j = 0; j < 4; j++) { a1h[i][j] = 0.f; a1m[i][j] = 0.f; a1l[i][j] = 0.f; }

#pragma unroll
        for (int s = 0; s < 8; s++) {
            unsigned ah[4], al[4], bh[4], bl[4];
            ldsm4(xa + s * 32, ah);
            ldsm4(xla + s * 32, al);
            ldsm4(w1b + s * 32, bh);
            ldsm4(w1b + W1HALF + s * 32, bl);
            mma16816(a1h[0], ah, bh);
            mma16816(a1m[0], ah, bl);
            mma16816(a1l[0], al, bh);
            mma16816(a1h[1], ah, bh + 2);
            mma16816(a1m[1], ah, bl + 2);
            mma16816(a1l[1], al, bh + 2);
        }

        // ---- epilogue: combine, GELU, split -> A2[c&1]
        {
            unsigned a2wh = sb - sb + 0;  // (silence unused warn pattern)
            (void)a2wh;
#pragma unroll
            for (int nf = 0; nf < 2; nf++) {
                float v0 = a1h[nf][0] + a1m[nf][0] + a1l[nf][0];
                float v1 = a1h[nf][1] + a1m[nf][1] + a1l[nf][1];
                float v2 = a1h[nf][2] + a1m[nf][2] + a1l[nf][2];
                float v3 = a1h[nf][3] + a1m[nf][3] + a1l[nf][3];
                int col = n0a + nf * 8 + tg * 2;
                unsigned hb = (unsigned)(c & 1) * A2BUF;
                unsigned hi, lo;
                bsplit2(gelu(v0), gelu(v1), hi, lo);
                *(unsigned*)(smem + OFF_A2 + hb + (m0 + g) * 80 + col * 2) = hi;
                *(unsigned*)(smem + OFF_A2 + hb + 5120 + (m0 + g) * 80 + col * 2) = lo;
                bsplit2(gelu(v2), gelu(v3), hi, lo);
                *(unsigned*)(smem + OFF_A2 + hb + (m0 + g + 8) * 80 + col * 2) = hi;
                *(unsigned*)(smem + OFF_A2 + hb + 5120 + (m0 + g + 8) * 80 + col * 2) = lo;
            }
        }
        CP_WAIT(0);  // W1(c+1) + W2(c) complete (this thread); visibility at next top sync
    }

    // ---- final GEMM2(NCHUNK-1)
    __syncthreads();
    {
        unsigned a2h = sb + OFF_A2 + (unsigned)((NCHUNK - 1) & 1) * A2BUF + a2row;
        unsigned a2l = a2h + 5120;
#pragma unroll
        for (int s = 0; s < 2; s++) {
            unsigned ah[4], al[4];
            ldsm4(a2h + s * 32, ah);
            ldsm4(a2l + s * 32, al);
#pragma unroll
            for (int q = 0; q < 4; q++) {
                unsigned bh[4], bl[4];
                ldsm4(b2a + q * 1280 + s * 32, bh);
                ldsm4(b2a + W2HALF + q * 1280 + s * 32, bl);
                mma16816(oacc[2 * q], ah, bh);
                mma16816(oacc[2 * q], ah, bl);
                mma16816(oacc[2 * q], al, bh);
                mma16816(oacc[2 * q + 1], ah, bh + 2);
                mma16816(oacc[2 * q + 1], ah, bl + 2);
                mma16816(oacc[2 * q + 1], al, bh + 2);
            }
        }
    }

    // ---- scatter output rows
#pragma unroll
    for (int nf = 0; nf < 8; nf++) {
        int col = n0b + nf * 8 + tg * 2;
        int m1 = m0 + g, m2 = m0 + g + 8;
        if (m1 < ntok) {
            int t = toks[m1];
            *reinterpret_cast<float2*>(out + (size_t)t * D_DIM + col) =
                make_float2(oacc[nf][0], oacc[nf][1]);
        }
        if (m2 < ntok) {
            int t = toks[m2];
            *reinterpret_cast<float2*>(out + (size_t)t * D_DIM + col) =
                make_float2(oacc[nf][2], oacc[nf][3]);
        }
    }
}

// ---------------- launcher ----------------
extern "C" void kernel_launch(void* const* d_in, const int* in_sizes, int n_in,
                              void* d_out, int out_size) {
    const float* x  = (const float*)d_in[0];
    const float* w1 = (const float*)d_in[1];
    const float* w2 = (const float*)d_in[2];
    const float* wg = (const float*)d_in[3];
    const float* bg = (const float*)d_in[4];
    float* out = (float*)d_out;

    cudaFuncSetAttribute(moe_mma_kernel, cudaFuncAttributeMaxDynamicSharedMemorySize,
                         SMEM_TOTAL);

    dim3 pgrid(E_EXP, NCHUNK);
    prep_kernel<<<pgrid, THREADS>>>(w1, w2);   // also zeroes g_cnt (block 0,0)
    router_kernel<<<B_TOK / THREADS, THREADS>>>(x, wg, bg);
    tile_kernel<<<1, THREADS>>>();
    moe_mma_kernel<<<MAX_TILES, THREADS, SMEM_TOTAL>>>(x, out);
}

// round 16
// speedup vs baseline: 1.2722x; 1.2658x over previous
#include <cuda_runtime.h>
#include <cuda_fp16.h>
#include <math.h>

#define B_TOK 32768
#define D_DIM 128
#define H_DIM 512
#define E_EXP 16
#define TM 64
#define NH 32
#define NCHUNK (H_DIM / NH)   // 16
#define THREADS 256
#define MAX_TILES 544

// weight image sizes (bytes) — single fp16 images (no hi/lo split)
#define W1CH 8704             // 32 h-rows x 272B (64 d-pair words + 4 pad words)
#define W2CH 10240            // 128 d-rows x 80B (16 j-pair words + 4 pad words)
#define CHUNK_BYTES (W1CH + W2CH)  // 18944

// SMEM layout (bytes)
#define OFF_TOKS 0
#define OFF_XH   256
#define OFF_XL   (OFF_XH + 17408)            // 17664
#define OFF_A2   (OFF_XL + 17408)            // 35072: 2 bufs x (Hh 5120 | Hl 5120)
#define A2BUF    10240
#define OFF_W1   (OFF_A2 + 2 * A2BUF)        // 55552: 2 bufs x W1CH
#define OFF_W2   (OFF_W1 + 2 * W1CH)         // 72960: single W2CH
#define SMEM_TOTAL (OFF_W2 + W2CH)           // 83200 -> 2 CTAs/SM

// ---------------- device scratch ----------------
__device__ int g_cnt[E_EXP];
__device__ int g_tok[E_EXP * B_TOK];
__device__ int g_ntiles;
__device__ int g_tile[MAX_TILES];
__device__ unsigned char g_wt[E_EXP][NCHUNK][CHUNK_BYTES];  // fp16 weight images

// ---------------- helpers ----------------
// fp16 hi/lo split of two floats: v = hi + lo with residual ~2^-24
__device__ __forceinline__ void hsplit2(float v0, float v1, unsigned& hi, unsigned& lo) {
    __half2 h = __floats2half2_rn(v0, v1);
    float r0 = v0 - __half2float(__low2half(h));
    float r1 = v1 - __half2float(__high2half(h));
    __half2 l = __floats2half2_rn(r0, r1);
    hi = *(unsigned*)&h;
    lo = *(unsigned*)&l;
}
__device__ __forceinline__ unsigned hpack2(float v0, float v1) {
    __half2 h = __floats2half2_rn(v0, v1);
    return *(unsigned*)&h;
}
__device__ __forceinline__ float gelu(float h) {
    return 0.5f * h * (1.0f + erff(h * 0.70710678118654752440f));
}
__device__ __forceinline__ unsigned smem_u32(const void* p) {
    unsigned a;
    asm("{ .reg .u64 t; cvta.to.shared.u64 t, %1; cvt.u32.u64 %0, t; }"
        : "=r"(a) : "l"(p));
    return a;
}
__device__ __forceinline__ void cp_async16(unsigned dst, const void* src) {
    asm volatile("cp.async.cg.shared.global [%0], [%1], 16;"
                 :: "r"(dst), "l"(src) : "memory");
}
#define CP_COMMIT() asm volatile("cp.async.commit_group;" ::: "memory")
#define CP_WAIT(n)  asm volatile("cp.async.wait_group %0;" :: "n"(n) : "memory")

// ldmatrix x4: four 8x8 b16 tiles
__device__ __forceinline__ void ldsm4(unsigned addr, unsigned* r) {
    asm volatile("ldmatrix.sync.aligned.m8n8.x4.shared.b16 {%0,%1,%2,%3}, [%4];"
                 : "=r"(r[0]), "=r"(r[1]), "=r"(r[2]), "=r"(r[3]) : "r"(addr));
}

// D += A * B  (m16n8k16, fp16 in, fp32 acc)
__device__ __forceinline__ void mma16816(float* c, const unsigned* a, const unsigned* b) {
    asm volatile(
        "mma.sync.aligned.m16n8k16.row.col.f32.f16.f16.f32 "
        "{%0,%1,%2,%3}, {%4,%5,%6,%7}, {%8,%9}, {%0,%1,%2,%3};"
        : "+f"(c[0]), "+f"(c[1]), "+f"(c[2]), "+f"(c[3])
        : "r"(a[0]), "r"(a[1]), "r"(a[2]), "r"(a[3]), "r"(b[0]), "r"(b[1]));
}

// ---------------- kernel P: fp16 weight images + zero counters ----------------
// W1 word (h, w<64): (fp16 w1[2w][h0+h], fp16 w1[2w+1][h0+h])
// W2 word (d, w<16): (fp16 w2[h0+2w][d], fp16 w2[h0+2w+1][d])
__global__ __launch_bounds__(THREADS) void prep_kernel(
    const float* __restrict__ w1, const float* __restrict__ w2) {
    if (blockIdx.x == 0 && blockIdx.y == 0 && threadIdx.x < E_EXP)
        g_cnt[threadIdx.x] = 0;
    int e = blockIdx.x, c = blockIdx.y;
    int h0 = c * NH;
    const float* w1e = w1 + (size_t)e * D_DIM * H_DIM;
    const float* w2e = w2 + (size_t)e * H_DIM * D_DIM;
    unsigned char* dst = g_wt[e][c];

    for (int i = threadIdx.x; i < W1CH / 4; i += THREADS) {  // 2176 words
        int h = i / 68, w = i % 68;
        if (w < 64) {
            float v0 = w1e[(size_t)(2 * w) * H_DIM + h0 + h];
            float v1 = w1e[(size_t)(2 * w + 1) * H_DIM + h0 + h];
            *(unsigned*)(dst + i * 4) = hpack2(v0, v1);
        }
    }
    for (int i = threadIdx.x; i < W2CH / 4; i += THREADS) {  // 2560 words
        int d = i / 20, w = i % 20;
        if (w < 16) {
            float v0 = w2e[(size_t)(h0 + 2 * w) * D_DIM + d];
            float v1 = w2e[(size_t)(h0 + 2 * w + 1) * D_DIM + d];
            *(unsigned*)(dst + W1CH + i * 4) = hpack2(v0, v1);
        }
    }
}

// ---------------- kernel 1: router (known-good) ----------------
__global__ __launch_bounds__(THREADS) void router_kernel(
    const float* __restrict__ x, const float* __restrict__ wg,
    const float* __restrict__ bg) {
    __shared__ float wgs[D_DIM * E_EXP];
    __shared__ float bgs[E_EXP];
    int tid = threadIdx.x;
    for (int i = tid; i < D_DIM * E_EXP; i += THREADS) wgs[i] = wg[i];
    if (tid < E_EXP) bgs[tid] = bg[tid];
    __syncthreads();

    int b = blockIdx.x * THREADS + tid;
    float acc[E_EXP];
#pragma unroll
    for (int e = 0; e < E_EXP; e++) acc[e] = bgs[e];
    const float4* xr = reinterpret_cast<const float4*>(x) + (size_t)b * (D_DIM / 4);
#pragma unroll 4
    for (int dq = 0; dq < D_DIM / 4; dq++) {
        float4 xv = xr[dq];
#pragma unroll
        for (int e = 0; e < E_EXP; e++) {
            acc[e] += xv.x * wgs[(dq * 4 + 0) * E_EXP + e];
            acc[e] += xv.y * wgs[(dq * 4 + 1) * E_EXP + e];
            acc[e] += xv.z * wgs[(dq * 4 + 2) * E_EXP + e];
            acc[e] += xv.w * wgs[(dq * 4 + 3) * E_EXP + e];
        }
    }
    int best = 0; float bv = acc[0];
#pragma unroll
    for (int e = 1; e < E_EXP; e++)
        if (acc[e] > bv) { bv = acc[e]; best = e; }

    unsigned lane = tid & 31;
    unsigned mask = __match_any_sync(0xffffffffu, best);
    int leader = __ffs(mask) - 1;
    int rank = __popc(mask & ((1u << lane) - 1u));
    int base = 0;
    if ((int)lane == leader) base = atomicAdd(&g_cnt[best], __popc(mask));
    base = __shfl_sync(0xffffffffu, base, leader);
    g_tok[best * B_TOK + base + rank] = b;
}

// ---------------- kernel T: build exact tile list ----------------
__global__ __launch_bounds__(THREADS) void tile_kernel() {
    __shared__ int offs[E_EXP + 1];
    int tid = threadIdx.x;
    if (tid == 0) {
        int s = 0;
#pragma unroll
        for (int e = 0; e < E_EXP; e++) {
            offs[e] = s;
            s += (g_cnt[e] + TM - 1) / TM;
        }
        offs[E_EXP] = s;
        g_ntiles = s;
    }
    __syncthreads();
#pragma unroll
    for (int e = 0; e < E_EXP; e++) {
        int o = offs[e], nt = offs[e + 1] - o;
        for (int i = tid; i < nt; i += THREADS)
            g_tile[o + i] = (e << 16) | i;
    }
}

// ---------------- kernel 2: pipelined grouped MLP (fp16 HMMA + LDSM) ----------------
__global__ __launch_bounds__(THREADS, 2) void moe_mma_kernel(
    const float* __restrict__ x, float* __restrict__ out) {
    extern __shared__ char smem[];
    int b = blockIdx.x;
    if (b >= g_ntiles) return;
    int desc = g_tile[b];
    int e = desc >> 16;
    int start = (desc & 0xffff) * TM;
    int cnt = g_cnt[e];
    int ntok = min(TM, cnt - start);
    int tid = threadIdx.x, wid = tid >> 5, lane = tid & 31;
    int g = lane >> 2, tg = lane & 3;
    int m0 = (wid & 3) * 16;
    int n0a = (wid >> 2) * 16;  // GEMM1 n-offset
    int n0b = (wid >> 2) * 64;  // GEMM2 n-offset
    unsigned sb = smem_u32(smem);

    int* toks = (int*)(smem + OFF_TOKS);
    if (tid < TM) toks[tid] = (tid < ntok) ? g_tok[e * B_TOK + start + tid] : -1;
    __syncthreads();

    // ---- prologue: issue W1(0) copy (overlaps X gather)
    {
        const unsigned char* src = g_wt[e][0];
        unsigned dst = sb + OFF_W1;
        for (int i = tid; i < W1CH / 16; i += THREADS)
            cp_async16(dst + i * 16, src + i * 16);
        CP_COMMIT();
    }

    // ---- gather X tile [64][128] fp32 -> fp16 hi/lo (row stride 272B)
    {
        int m = tid >> 2, q4 = tid & 3;
        int t = toks[m];
        const float4* xr = reinterpret_cast<const float4*>(x) +
                           (size_t)(t < 0 ? 0 : t) * 32 + q4 * 8;
#pragma unroll
        for (int i = 0; i < 8; i++) {
            float4 v = (t >= 0) ? xr[i] : make_float4(0.f, 0.f, 0.f, 0.f);
            int d = q4 * 32 + i * 4;
            unsigned hi, lo;
            hsplit2(v.x, v.y, hi, lo);
            *(unsigned*)(smem + OFF_XH + m * 272 + d * 2) = hi;
            *(unsigned*)(smem + OFF_XL + m * 272 + d * 2) = lo;
            hsplit2(v.z, v.w, hi, lo);
            *(unsigned*)(smem + OFF_XH + m * 272 + d * 2 + 4) = hi;
            *(unsigned*)(smem + OFF_XL + m * 272 + d * 2 + 4) = lo;
        }
    }
    CP_WAIT(0);   // W1(0) complete (this thread)

    // ---- per-thread LDSM base addresses (hoisted)
    unsigned xa = sb + OFF_XH +
                  (unsigned)(m0 + ((lane >> 3) & 1) * 8 + (lane & 7)) * 272 +
                  ((lane >> 4) & 1) * 16;
    unsigned xla = xa + (OFF_XL - OFF_XH);
    unsigned b1off = (unsigned)(n0a + ((lane >> 4) & 1) * 8 + (lane & 7)) * 272 +
                     ((lane >> 3) & 1) * 16;
    unsigned a2row = (unsigned)(m0 + ((lane >> 3) & 1) * 8 + (lane & 7)) * 80 +
                     ((lane >> 4) & 1) * 16;   // + OFF_A2 + parity*A2BUF (+5120 for lo)
    unsigned b2a = sb + OFF_W2 +
                   (unsigned)(n0b + ((lane >> 4) & 1) * 8 + (lane & 7)) * 80 +
                   ((lane >> 3) & 1) * 16;

    float oacc[8][4];
#pragma unroll
    for (int i = 0; i < 8; i++)
#pragma unroll
        for (int j = 0; j < 4; j++) oacc[i][j] = 0.f;

    for (int c = 0; c < NCHUNK; c++) {
        __syncthreads();  // prev copies/epilogue visible; W1 buf[(c+1)&1] + A2[c&1] free

        // prefetch W1(c+1) into the other W1 buffer (overlaps GEMM2 + GEMM1)
        {
            int cn = (c + 1) & (NCHUNK - 1);
            const unsigned char* s1 = g_wt[e][cn];
            unsigned d1 = sb + OFF_W1 + ((c + 1) & 1) * W1CH;
            for (int i = tid; i < W1CH / 16; i += THREADS)
                cp_async16(d1 + i * 16, s1 + i * 16);
            CP_COMMIT();
        }

        // ---- GEMM2(c-1): oacc += H(c-1) @ W2(c-1)^T   [A2 parity (c-1)&1]
        if (c > 0) {
            unsigned a2h = sb + OFF_A2 + (unsigned)((c - 1) & 1) * A2BUF + a2row;
            unsigned a2l = a2h + 5120;
#pragma unroll
            for (int s = 0; s < 2; s++) {
                unsigned ah[4], al[4];
                ldsm4(a2h + s * 32, ah);
                ldsm4(a2l + s * 32, al);
#pragma unroll
                for (int q = 0; q < 4; q++) {
                    unsigned bh[4];
                    ldsm4(b2a + q * 1280 + s * 32, bh);
                    mma16816(oacc[2 * q], ah, bh);
                    mma16816(oacc[2 * q], al, bh);
                    mma16816(oacc[2 * q + 1], ah, bh + 2);
                    mma16816(oacc[2 * q + 1], al, bh + 2);
                }
            }
        }
        __syncthreads();  // W2 buffer free (all warps done with W2(c-1))

        // copy W2(c) (overlaps GEMM1)
        {
            const unsigned char* s2 = g_wt[e][c] + W1CH;
            unsigned d2 = sb + OFF_W2;
            for (int i = tid; i < W2CH / 16; i += THREADS)
                cp_async16(d2 + i * 16, s2 + i * 16);
            CP_COMMIT();
        }

        unsigned w1b = sb + OFF_W1 + (c & 1) * W1CH + b1off;

        // ---- GEMM1(c): 4 independent chains (hi/lo x 2 n-frags)
        float a1h[2][4], a1l[2][4];
#pragma unroll
        for (int i = 0; i < 2; i++)
#pragma unroll
            for (int j = 0; j < 4; j++) { a1h[i][j] = 0.f; a1l[i][j] = 0.f; }

#pragma unroll
        for (int s = 0; s < 8; s++) {
            unsigned ah[4], al[4], bh[4];
            ldsm4(xa + s * 32, ah);
            ldsm4(xla + s * 32, al);
            ldsm4(w1b + s * 32, bh);
            mma16816(a1h[0], ah, bh);
            mma16816(a1l[0], al, bh);
            mma16816(a1h[1], ah, bh + 2);
            mma16816(a1l[1], al, bh + 2);
        }

        // ---- epilogue: combine, GELU, fp16 split -> A2[c&1]
#pragma unroll
        for (int nf = 0; nf < 2; nf++) {
            float v0 = a1h[nf][0] + a1l[nf][0];
            float v1 = a1h[nf][1] + a1l[nf][1];
            float v2 = a1h[nf][2] + a1l[nf][2];
            float v3 = a1h[nf][3] + a1l[nf][3];
            int col = n0a + nf * 8 + tg * 2;
            unsigned hb = (unsigned)(c & 1) * A2BUF;
            unsigned hi, lo;
            hsplit2(gelu(v0), gelu(v1), hi, lo);
            *(unsigned*)(smem + OFF_A2 + hb + (m0 + g) * 80 + col * 2) = hi;
            *(unsigned*)(smem + OFF_A2 + hb + 5120 + (m0 + g) * 80 + col * 2) = lo;
            hsplit2(gelu(v2), gelu(v3), hi, lo);
            *(unsigned*)(smem + OFF_A2 + hb + (m0 + g + 8) * 80 + col * 2) = hi;
            *(unsigned*)(smem + OFF_A2 + hb + 5120 + (m0 + g + 8) * 80 + col * 2) = lo;
        }
        CP_WAIT(0);  // W1(c+1) + W2(c) complete (this thread); visibility at next top sync
    }

    // ---- final GEMM2(NCHUNK-1)
    __syncthreads();
    {
        unsigned a2h = sb + OFF_A2 + (unsigned)((NCHUNK - 1) & 1) * A2BUF + a2row;
        unsigned a2l = a2h + 5120;
#pragma unroll
        for (int s = 0; s < 2; s++) {
            unsigned ah[4], al[4];
            ldsm4(a2h + s * 32, ah);
            ldsm4(a2l + s * 32, al);
#pragma unroll
            for (int q = 0; q < 4; q++) {
                unsigned bh[4];
                ldsm4(b2a + q * 1280 + s * 32, bh);
                mma16816(oacc[2 * q], ah, bh);
                mma16816(oacc[2 * q], al, bh);
                mma16816(oacc[2 * q + 1], ah, bh + 2);
                mma16816(oacc[2 * q + 1], al, bh + 2);
            }
        }
    }

    // ---- scatter output rows
#pragma unroll
    for (int nf = 0; nf < 8; nf++) {
        int col = n0b + nf * 8 + tg * 2;
        int m1 = m0 + g, m2 = m0 + g + 8;
        if (m1 < ntok) {
            int t = toks[m1];
            *reinterpret_cast<float2*>(out + (size_t)t * D_DIM + col) =
                make_float2(oacc[nf][0], oacc[nf][1]);
        }
        if (m2 < ntok) {
            int t = toks[m2];
            *reinterpret_cast<float2*>(out + (size_t)t * D_DIM + col) =
                make_float2(oacc[nf][2], oacc[nf][3]);
        }
    }
}

// ---------------- launcher ----------------
extern "C" void kernel_launch(void* const* d_in, const int* in_sizes, int n_in,
                              void* d_out, int out_size) {
    const float* x  = (const float*)d_in[0];
    const float* w1 = (const float*)d_in[1];
    const float* w2 = (const float*)d_in[2];
    const float* wg = (const float*)d_in[3];
    const float* bg = (const float*)d_in[4];
    float* out = (float*)d_out;

    cudaFuncSetAttribute(moe_mma_kernel, cudaFuncAttributeMaxDynamicSharedMemorySize,
                         SMEM_TOTAL);

    dim3 pgrid(E_EXP, NCHUNK);
    prep_kernel<<<pgrid, THREADS>>>(w1, w2);   // also zeroes g_cnt (block 0,0)
    router_kernel<<<B_TOK / THREADS, THREADS>>>(x, wg, bg);
    tile_kernel<<<1, THREADS>>>();
    moe_mma_kernel<<<MAX_TILES, THREADS, SMEM_TOTAL>>>(x, out);
}

// round 17
// speedup vs baseline: 1.3837x; 1.0877x over previous
#include <cuda_runtime.h>
#include <cuda_fp16.h>
#include <math.h>

#define B_TOK 32768
#define D_DIM 128
#define H_DIM 512
#define E_EXP 16
#define TM 64
#define NH 32
#define NCHUNK (H_DIM / NH)   // 16
#define THREADS 256
#define MAX_TILES 544

// weight image sizes (bytes) — single fp16 images
#define W1CH 8704             // 32 h-rows x 272B (64 d-pair words + 4 pad words)
#define W2CH 10240            // 128 d-rows x 80B (16 j-pair words + 4 pad words)
#define CHUNK_BYTES (W1CH + W2CH)  // 18944

// SMEM layout (bytes)
#define OFF_TOKS 0
#define OFF_XH   256
#define OFF_XL   (OFF_XH + 17408)            // 17664
#define OFF_A2   (OFF_XL + 17408)            // 35072: 2 parity bufs x 5120 (fp16 only)
#define A2BUF    5120
#define OFF_W1   (OFF_A2 + 2 * A2BUF)        // 45312: 2 bufs x W1CH
#define OFF_W2   (OFF_W1 + 2 * W1CH)         // 62720: single W2CH
#define SMEM_TOTAL (OFF_W2 + W2CH)           // 72960 -> 2 CTAs/SM

// ---------------- device scratch ----------------
__device__ int g_cnt[E_EXP];
__device__ int g_tok[E_EXP * B_TOK];
__device__ int g_ntiles;
__device__ int g_tile[MAX_TILES];
__device__ unsigned char g_wt[E_EXP][NCHUNK][CHUNK_BYTES];  // fp16 weight images

// ---------------- helpers ----------------
__device__ __forceinline__ void hsplit2(float v0, float v1, unsigned& hi, unsigned& lo) {
    __half2 h = __floats2half2_rn(v0, v1);
    float r0 = v0 - __half2float(__low2half(h));
    float r1 = v1 - __half2float(__high2half(h));
    __half2 l = __floats2half2_rn(r0, r1);
    hi = *(unsigned*)&h;
    lo = *(unsigned*)&l;
}
__device__ __forceinline__ unsigned hpack2(float v0, float v1) {
    __half2 h = __floats2half2_rn(v0, v1);
    return *(unsigned*)&h;
}
__device__ __forceinline__ float gelu(float h) {
    return 0.5f * h * (1.0f + erff(h * 0.70710678118654752440f));
}
__device__ __forceinline__ unsigned smem_u32(const void* p) {
    unsigned a;
    asm("{ .reg .u64 t; cvta.to.shared.u64 t, %1; cvt.u32.u64 %0, t; }"
        : "=r"(a) : "l"(p));
    return a;
}
__device__ __forceinline__ void cp_async16(unsigned dst, const void* src) {
    asm volatile("cp.async.cg.shared.global [%0], [%1], 16;"
                 :: "r"(dst), "l"(src) : "memory");
}
#define CP_COMMIT() asm volatile("cp.async.commit_group;" ::: "memory")
#define CP_WAIT(n)  asm volatile("cp.async.wait_group %0;" :: "n"(n) : "memory")

// ldmatrix x4: four 8x8 b16 tiles
__device__ __forceinline__ void ldsm4(unsigned addr, unsigned* r) {
    asm volatile("ldmatrix.sync.aligned.m8n8.x4.shared.b16 {%0,%1,%2,%3}, [%4];"
                 : "=r"(r[0]), "=r"(r[1]), "=r"(r[2]), "=r"(r[3]) : "r"(addr));
}

// D += A * B  (m16n8k16, fp16 in, fp32 acc)
__device__ __forceinline__ void mma16816(float* c, const unsigned* a, const unsigned* b) {
    asm volatile(
        "mma.sync.aligned.m16n8k16.row.col.f32.f16.f16.f32 "
        "{%0,%1,%2,%3}, {%4,%5,%6,%7}, {%8,%9}, {%0,%1,%2,%3};"
        : "+f"(c[0]), "+f"(c[1]), "+f"(c[2]), "+f"(c[3])
        : "r"(a[0]), "r"(a[1]), "r"(a[2]), "r"(a[3]), "r"(b[0]), "r"(b[1]));
}

// ---------------- kernel P: fp16 weight images + zero counters ----------------
__global__ __launch_bounds__(THREADS) void prep_kernel(
    const float* __restrict__ w1, const float* __restrict__ w2) {
    if (blockIdx.x == 0 && blockIdx.y == 0 && threadIdx.x < E_EXP)
        g_cnt[threadIdx.x] = 0;
    int e = blockIdx.x, c = blockIdx.y;
    int h0 = c * NH;
    const float* w1e = w1 + (size_t)e * D_DIM * H_DIM;
    const float* w2e = w2 + (size_t)e * H_DIM * D_DIM;
    unsigned char* dst = g_wt[e][c];

    for (int i = threadIdx.x; i < W1CH / 4; i += THREADS) {  // 2176 words
        int h = i / 68, w = i % 68;
        if (w < 64) {
            float v0 = w1e[(size_t)(2 * w) * H_DIM + h0 + h];
            float v1 = w1e[(size_t)(2 * w + 1) * H_DIM + h0 + h];
            *(unsigned*)(dst + i * 4) = hpack2(v0, v1);
        }
    }
    for (int i = threadIdx.x; i < W2CH / 4; i += THREADS) {  // 2560 words
        int d = i / 20, w = i % 20;
        if (w < 16) {
            float v0 = w2e[(size_t)(h0 + 2 * w) * D_DIM + d];
            float v1 = w2e[(size_t)(h0 + 2 * w + 1) * D_DIM + d];
            *(unsigned*)(dst + W1CH + i * 4) = hpack2(v0, v1);
        }
    }
}

// ---------------- kernel 1: router (known-good) ----------------
__global__ __launch_bounds__(THREADS) void router_kernel(
    const float* __restrict__ x, const float* __restrict__ wg,
    const float* __restrict__ bg) {
    __shared__ float wgs[D_DIM * E_EXP];
    __shared__ float bgs[E_EXP];
    int tid = threadIdx.x;
    for (int i = tid; i < D_DIM * E_EXP; i += THREADS) wgs[i] = wg[i];
    if (tid < E_EXP) bgs[tid] = bg[tid];
    __syncthreads();

    int b = blockIdx.x * THREADS + tid;
    float acc[E_EXP];
#pragma unroll
    for (int e = 0; e < E_EXP; e++) acc[e] = bgs[e];
    const float4* xr = reinterpret_cast<const float4*>(x) + (size_t)b * (D_DIM / 4);
#pragma unroll 4
    for (int dq = 0; dq < D_DIM / 4; dq++) {
        float4 xv = xr[dq];
#pragma unroll
        for (int e = 0; e < E_EXP; e++) {
            acc[e] += xv.x * wgs[(dq * 4 + 0) * E_EXP + e];
            acc[e] += xv.y * wgs[(dq * 4 + 1) * E_EXP + e];
            acc[e] += xv.z * wgs[(dq * 4 + 2) * E_EXP + e];
            acc[e] += xv.w * wgs[(dq * 4 + 3) * E_EXP + e];
        }
    }
    int best = 0; float bv = acc[0];
#pragma unroll
    for (int e = 1; e < E_EXP; e++)
        if (acc[e] > bv) { bv = acc[e]; best = e; }

    unsigned lane = tid & 31;
    unsigned mask = __match_any_sync(0xffffffffu, best);
    int leader = __ffs(mask) - 1;
    int rank = __popc(mask & ((1u << lane) - 1u));
    int base = 0;
    if ((int)lane == leader) base = atomicAdd(&g_cnt[best], __popc(mask));
    base = __shfl_sync(0xffffffffu, base, leader);
    g_tok[best * B_TOK + base + rank] = b;
}

// ---------------- kernel T: build exact tile list ----------------
__global__ __launch_bounds__(THREADS) void tile_kernel() {
    __shared__ int offs[E_EXP + 1];
    int tid = threadIdx.x;
    if (tid == 0) {
        int s = 0;
#pragma unroll
        for (int e = 0; e < E_EXP; e++) {
            offs[e] = s;
            s += (g_cnt[e] + TM - 1) / TM;
        }
        offs[E_EXP] = s;
        g_ntiles = s;
    }
    __syncthreads();
#pragma unroll
    for (int e = 0; e < E_EXP; e++) {
        int o = offs[e], nt = offs[e + 1] - o;
        for (int i = tid; i < nt; i += THREADS)
            g_tile[o + i] = (e << 16) | i;
    }
}

// ---------------- kernel 2: pipelined grouped MLP (fp16 HMMA + LDSM) ----------------
__global__ __launch_bounds__(THREADS, 2) void moe_mma_kernel(
    const float* __restrict__ x, float* __restrict__ out) {
    extern __shared__ char smem[];
    int b = blockIdx.x;
    if (b >= g_ntiles) return;
    int desc = g_tile[b];
    int e = desc >> 16;
    int start = (desc & 0xffff) * TM;
    int cnt = g_cnt[e];
    int ntok = min(TM, cnt - start);
    int tid = threadIdx.x, wid = tid >> 5, lane = tid & 31;
    int g = lane >> 2, tg = lane & 3;
    int m0 = (wid & 3) * 16;
    int n0a = (wid >> 2) * 16;  // GEMM1 n-offset
    int n0b = (wid >> 2) * 64;  // GEMM2 n-offset
    unsigned sb = smem_u32(smem);

    int* toks = (int*)(smem + OFF_TOKS);
    if (tid < TM) toks[tid] = (tid < ntok) ? g_tok[e * B_TOK + start + tid] : -1;
    __syncthreads();

    // ---- prologue: issue W1(0) copy (overlaps X gather)
    {
        const unsigned char* src = g_wt[e][0];
        unsigned dst = sb + OFF_W1;
        for (int i = tid; i < W1CH / 16; i += THREADS)
            cp_async16(dst + i * 16, src + i * 16);
        CP_COMMIT();
    }

    // ---- gather X tile [64][128] fp32 -> fp16 hi/lo (row stride 272B)
    {
        int m = tid >> 2, q4 = tid & 3;
        int t = toks[m];
        const float4* xr = reinterpret_cast<const float4*>(x) +
                           (size_t)(t < 0 ? 0 : t) * 32 + q4 * 8;
#pragma unroll
        for (int i = 0; i < 8; i++) {
            float4 v = (t >= 0) ? xr[i] : make_float4(0.f, 0.f, 0.f, 0.f);
            int d = q4 * 32 + i * 4;
            unsigned hi, lo;
            hsplit2(v.x, v.y, hi, lo);
            *(unsigned*)(smem + OFF_XH + m * 272 + d * 2) = hi;
            *(unsigned*)(smem + OFF_XL + m * 272 + d * 2) = lo;
            hsplit2(v.z, v.w, hi, lo);
            *(unsigned*)(smem + OFF_XH + m * 272 + d * 2 + 4) = hi;
            *(unsigned*)(smem + OFF_XL + m * 272 + d * 2 + 4) = lo;
        }
    }
    CP_WAIT(0);   // W1(0) complete (this thread)

    // ---- per-thread LDSM base addresses (hoisted)
    unsigned xa = sb + OFF_XH +
                  (unsigned)(m0 + ((lane >> 3) & 1) * 8 + (lane & 7)) * 272 +
                  ((lane >> 4) & 1) * 16;
    unsigned xla = xa + (OFF_XL - OFF_XH);
    unsigned b1off = (unsigned)(n0a + ((lane >> 4) & 1) * 8 + (lane & 7)) * 272 +
                     ((lane >> 3) & 1) * 16;
    unsigned a2row = (unsigned)(m0 + ((lane >> 3) & 1) * 8 + (lane & 7)) * 80 +
                     ((lane >> 4) & 1) * 16;   // + OFF_A2 + parity*A2BUF
    unsigned b2a = sb + OFF_W2 +
                   (unsigned)(n0b + ((lane >> 4) & 1) * 8 + (lane & 7)) * 80 +
                   ((lane >> 3) & 1) * 16;

    float oacc[8][4];
#pragma unroll
    for (int i = 0; i < 8; i++)
#pragma unroll
        for (int j = 0; j < 4; j++) oacc[i][j] = 0.f;

    for (int c = 0; c < NCHUNK; c++) {
        __syncthreads();  // prev copies/epilogue visible; W1 buf[(c+1)&1] + A2[c&1] free

        // prefetch W1(c+1) into the other W1 buffer (overlaps GEMM2 + GEMM1)
        {
            int cn = (c + 1) & (NCHUNK - 1);
            const unsigned char* s1 = g_wt[e][cn];
            unsigned d1 = sb + OFF_W1 + ((c + 1) & 1) * W1CH;
            for (int i = tid; i < W1CH / 16; i += THREADS)
                cp_async16(d1 + i * 16, s1 + i * 16);
            CP_COMMIT();
        }

        // ---- GEMM2(c-1): oacc += H(c-1) @ W2(c-1)^T   [A2 parity (c-1)&1]
        if (c > 0) {
            unsigned a2h = sb + OFF_A2 + (unsigned)((c - 1) & 1) * A2BUF + a2row;
#pragma unroll
            for (int s = 0; s < 2; s++) {
                unsigned ah[4];
                ldsm4(a2h + s * 32, ah);
#pragma unroll
                for (int q = 0; q < 4; q++) {
                    unsigned bh[4];
                    ldsm4(b2a + q * 1280 + s * 32, bh);
                    mma16816(oacc[2 * q], ah, bh);
                    mma16816(oacc[2 * q + 1], ah, bh + 2);
                }
            }
        }
        __syncthreads();  // W2 buffer free (all warps done with W2(c-1))

        // copy W2(c) (overlaps GEMM1)
        {
            const unsigned char* s2 = g_wt[e][c] + W1CH;
            unsigned d2 = sb + OFF_W2;
            for (int i = tid; i < W2CH / 16; i += THREADS)
                cp_async16(d2 + i * 16, s2 + i * 16);
            CP_COMMIT();
        }

        unsigned w1b = sb + OFF_W1 + (c & 1) * W1CH + b1off;

        // ---- GEMM1(c): 4 independent chains (X hi/lo x 2 n-frags)
        float a1h[2][4], a1l[2][4];
#pragma unroll
        for (int i = 0; i < 2; i++)
#pragma unroll
            for (int j = 0; j < 4; j++) { a1h[i][j] = 0.f; a1l[i][j] = 0.f; }

#pragma unroll
        for (int s = 0; s < 8; s++) {
            unsigned ah[4], al[4], bh[4];
            ldsm4(xa + s * 32, ah);
            ldsm4(xla + s * 32, al);
            ldsm4(w1b + s * 32, bh);
            mma16816(a1h[0], ah, bh);
            mma16816(a1l[0], al, bh);
            mma16816(a1h[1], ah, bh + 2);
            mma16816(a1l[1], al, bh + 2);
        }

        // ---- epilogue: combine, GELU, fp16 pack -> A2[c&1]
#pragma unroll
        for (int nf = 0; nf < 2; nf++) {
            float v0 = a1h[nf][0] + a1l[nf][0];
            float v1 = a1h[nf][1] + a1l[nf][1];
            float v2 = a1h[nf][2] + a1l[nf][2];
            float v3 = a1h[nf][3] + a1l[nf][3];
            int col = n0a + nf * 8 + tg * 2;
            unsigned hb = (unsigned)(c & 1) * A2BUF;
            *(unsigned*)(smem + OFF_A2 + hb + (m0 + g) * 80 + col * 2) =
                hpack2(gelu(v0), gelu(v1));
            *(unsigned*)(smem + OFF_A2 + hb + (m0 + g + 8) * 80 + col * 2) =
                hpack2(gelu(v2), gelu(v3));
        }
        CP_WAIT(0);  // W1(c+1) + W2(c) complete (this thread); visibility at next top sync
    }

    // ---- final GEMM2(NCHUNK-1)
    __syncthreads();
    {
        unsigned a2h = sb + OFF_A2 + (unsigned)((NCHUNK - 1) & 1) * A2BUF + a2row;
#pragma unroll
        for (int s = 0; s < 2; s++) {
            unsigned ah[4];
            ldsm4(a2h + s * 32, ah);
#pragma unroll
            for (int q = 0; q < 4; q++) {
                unsigned bh[4];
                ldsm4(b2a + q * 1280 + s * 32, bh);
                mma16816(oacc[2 * q], ah, bh);
                mma16816(oacc[2 * q + 1], ah, bh + 2);
            }
        }
    }

    // ---- scatter output rows
#pragma unroll
    for (int nf = 0; nf < 8; nf++) {
        int col = n0b + nf * 8 + tg * 2;
        int m1 = m0 + g, m2 = m0 + g + 8;
        if (m1 < ntok) {
            int t = toks[m1];
            *reinterpret_cast<float2*>(out + (size_t)t * D_DIM + col) =
                make_float2(oacc[nf][0], oacc[nf][1]);
        }
        if (m2 < ntok) {
            int t = toks[m2];
            *reinterpret_cast<float2*>(out + (size_t)t * D_DIM + col) =
                make_float2(oacc[nf][2], oacc[nf][3]);
        }
    }
}

// ---------------- launcher ----------------
extern "C" void kernel_launch(void* const* d_in, const int* in_sizes, int n_in,
                              void* d_out, int out_size) {
    const float* x  = (const float*)d_in[0];
    const float* w1 = (const float*)d_in[1];
    const float* w2 = (const float*)d_in[2];
    const float* wg = (const float*)d_in[3];
    const float* bg = (const float*)d_in[4];
    float* out = (float*)d_out;

    cudaFuncSetAttribute(moe_mma_kernel, cudaFuncAttributeMaxDynamicSharedMemorySize,
                         SMEM_TOTAL);

    dim3 pgrid(E_EXP, NCHUNK);
    prep_kernel<<<pgrid, THREADS>>>(w1, w2);   // also zeroes g_cnt (block 0,0)
    router_kernel<<<B_TOK / THREADS, THREADS>>>(x, wg, bg);
    tile_kernel<<<1, THREADS>>>();
    moe_mma_kernel<<<MAX_TILES, THREADS, SMEM_TOTAL>>>(x, out);
}